// round 11
// baseline (speedup 1.0000x reference)
#include <cuda_runtime.h>
#include <math.h>

// out[i,j] = | prod_k cos((x_ik - y_jk)/2) |
//          = | Px_i * Py_j * prod_k (1 + tan(x_ik/2) * tan(y_jk/2)) |
// 128x128 tile, 256 threads, blocked 8x8 outputs/thread, all-LDS.128 feed.

typedef unsigned long long u64;

__device__ __forceinline__ u64 fma2(u64 a, u64 b, u64 c) {
    u64 d;
    asm("fma.rn.f32x2 %0, %1, %2, %3;" : "=l"(d) : "l"(a), "l"(b), "l"(c));
    return d;
}
__device__ __forceinline__ u64 mul2(u64 a, u64 b) {
    u64 d;
    asm("mul.rn.f32x2 %0, %1, %2;" : "=l"(d) : "l"(a), "l"(b));
    return d;
}
__device__ __forceinline__ u64 dup2(float x) {
    u64 d;
    asm("mov.b64 %0, {%1, %2};" : "=l"(d) : "f"(x), "f"(x));
    return d;
}

__global__ __launch_bounds__(256, 2)
void qk_fused(const float* __restrict__ x, const float* __restrict__ y,
              float* __restrict__ out, int n, int m) {
    __shared__ __align__(16) u64   s_xt[16][128];  // [k][i] = (tanx,tanx) 16KB
    __shared__ __align__(16) float s_yt[16][128];  // [k][j] = tany         8KB
    __shared__ __align__(16) u64   s_px[128];      // (Px_i,Px_i)           1KB
    __shared__ __align__(16) float s_py[128];      // Py_j                  .5KB

    const int tid = threadIdx.x;
    const int i0 = blockIdx.y * 128;
    const int j0 = blockIdx.x * 128;

    // Prologue: thread t<128 -> x-row t; t>=128 -> y-row t-128. 16 sincos each.
    {
        int r = tid & 127;
        bool isx = tid < 128;
        const float* src = isx ? (x + (size_t)(i0 + r) * 16)
                               : (y + (size_t)(j0 + r) * 16);
        float4 v0 = ((const float4*)src)[0];
        float4 v1 = ((const float4*)src)[1];
        float4 v2 = ((const float4*)src)[2];
        float4 v3 = ((const float4*)src)[3];
        float vv[16] = {v0.x, v0.y, v0.z, v0.w, v1.x, v1.y, v1.z, v1.w,
                        v2.x, v2.y, v2.z, v2.w, v3.x, v3.y, v3.z, v3.w};
        float prod = 1.0f;
        #pragma unroll
        for (int k = 0; k < 16; k++) {
            float s, c;
            __sincosf(0.5f * vv[k], &s, &c);
            prod *= c;
            float t = __fdividef(s, c);
            if (isx) s_xt[k][r] = dup2(t);
            else     s_yt[k][r] = t;
        }
        if (isx) s_px[r] = dup2(prod);
        else     s_py[r] = prod;
    }
    __syncthreads();

    const int tx = tid & 15;   // j = 8*tx + 0..7  (4 f32x2 pairs, contiguous)
    const int ty = tid >> 4;   // i = 8*ty + 0..7  (8 rows, contiguous)

    u64 acc[8][4];
    const u64 ONE2 = 0x3f8000003f800000ULL;
    #pragma unroll
    for (int ii = 0; ii < 8; ii++)
        #pragma unroll
        for (int jj = 0; jj < 4; jj++) acc[ii][jj] = ONE2;

    #pragma unroll
    for (int k = 0; k < 16; k++) {
        // y: 8 contiguous tans = 4 pairs via 2 LDS.128
        ulonglong2 yq0 = *(const ulonglong2*)&s_yt[k][8 * tx];
        ulonglong2 yq1 = *(const ulonglong2*)&s_yt[k][8 * tx + 4];
        u64 yt[4] = {yq0.x, yq0.y, yq1.x, yq1.y};
        // x: 8 contiguous dup-pairs via 4 LDS.128 (8 distinct 16B/warp)
        u64 xt[8];
        #pragma unroll
        for (int q = 0; q < 4; q++) {
            ulonglong2 xq = *(const ulonglong2*)&s_xt[k][8 * ty + 2 * q];
            xt[2 * q] = xq.x;
            xt[2 * q + 1] = xq.y;
        }
        #pragma unroll
        for (int ii = 0; ii < 8; ii++)
            #pragma unroll
            for (int jj = 0; jj < 4; jj++) {
                u64 p = mul2(xt[ii], yt[jj]);                     // rt 2
                acc[ii][jj] = fma2(acc[ii][jj], p, acc[ii][jj]);  // rt 2
            }
    }

    // Epilogue: scale by Px_i * Py_j, abs, STG.128 x2 per row.
    ulonglong2 pyq0 = *(const ulonglong2*)&s_py[8 * tx];
    ulonglong2 pyq1 = *(const ulonglong2*)&s_py[8 * tx + 4];
    u64 py[4] = {pyq0.x, pyq0.y, pyq1.x, pyq1.y};
    #pragma unroll
    for (int ii = 0; ii < 8; ii++) {
        int i = i0 + 8 * ty + ii;
        u64 px = s_px[8 * ty + ii];
        float* orow = out + (size_t)i * m + j0 + 8 * tx;
        ulonglong2 v0, v1;
        v0.x = mul2(mul2(acc[ii][0], px), py[0]) & 0x7fffffff7fffffffULL;
        v0.y = mul2(mul2(acc[ii][1], px), py[1]) & 0x7fffffff7fffffffULL;
        v1.x = mul2(mul2(acc[ii][2], px), py[2]) & 0x7fffffff7fffffffULL;
        v1.y = mul2(mul2(acc[ii][3], px), py[3]) & 0x7fffffff7fffffffULL;
        *(ulonglong2*)(orow)     = v0;
        *(ulonglong2*)(orow + 4) = v1;
    }
}

// Generic fallback for unexpected shapes.
__global__ void qk_naive(const float* __restrict__ x, const float* __restrict__ y,
                         float* __restrict__ out, int n, int m, int d) {
    int j = blockIdx.x * blockDim.x + threadIdx.x;
    int i = blockIdx.y;
    if (i >= n || j >= m) return;
    float p = 1.0f;
    for (int k = 0; k < d; k++)
        p *= cosf(0.5f * (x[i * d + k] - y[j * d + k]));
    out[(size_t)i * m + j] = fabsf(p);
}

extern "C" void kernel_launch(void* const* d_in, const int* in_sizes, int n_in,
                              void* d_out, int out_size) {
    const float* x = (const float*)d_in[0];
    const float* y = (const float*)d_in[1];
    float* out = (float*)d_out;

    long long sx = in_sizes[0], sy = in_sizes[1], so = out_size;
    int d = (int)llround(sqrt((double)sx * (double)sy / (double)so));
    if (d <= 0) d = 16;
    int n = (int)(sx / d);
    int m = (int)(sy / d);

    if (d == 16 && n % 128 == 0 && m % 128 == 0) {
        dim3 grid(m / 128, n / 128);
        qk_fused<<<grid, 256>>>(x, y, out, n, m);
    } else {
        qk_naive<<<dim3((m + 255) / 256, n), 256>>>(x, y, out, n, m, d);
    }
}